// round 2
// baseline (speedup 1.0000x reference)
#include <cuda_runtime.h>
#include <cuda_bf16.h>
#include <mma.h>

using namespace nvcuda;

// Problem constants
#define BB   2048
#define TT   512
#define FF   64
#define HH   16
#define G4   64            // 4*H
#define BT   (BB * TT)     // 1,048,576 rows of x

// 256 MiB scratch for the precomputed input projection xz = x @ Wx
__device__ float g_xz[(long)BT * G4];

// ---------------------------------------------------------------------------
// Kernel A: xz = x @ Wx   (tf32 WMMA, bias deferred to kernel B)
// Tile: 64 rows x 64 cols per block, 256 threads (8 warps in 4x2 layout).
// ---------------------------------------------------------------------------
#define ROWS_PER_BLK 64
#define PAD 72   // 64 + 8 padding, multiple of 8 for ldm + conflict avoidance

__global__ __launch_bounds__(256) void xz_gemm_kernel(
    const float* __restrict__ x, const float* __restrict__ Wx)
{
    __shared__ float xs[ROWS_PER_BLK * PAD];
    __shared__ float ws[FF * PAD];

    const int tid = threadIdx.x;
    const long row0 = (long)blockIdx.x * ROWS_PER_BLK;

    // Stage x tile (64x64) as float4, coalesced
    const float4* xg = (const float4*)(x + row0 * FF);
    #pragma unroll
    for (int i = tid; i < ROWS_PER_BLK * 16; i += 256) {
        int r = i >> 4, c = i & 15;
        float4 v = xg[r * 16 + c];
        float* dst = &xs[r * PAD + c * 4];
        dst[0] = v.x; dst[1] = v.y; dst[2] = v.z; dst[3] = v.w;
    }
    // Stage Wx (64x64)
    const float4* wg = (const float4*)Wx;
    #pragma unroll
    for (int i = tid; i < FF * 16; i += 256) {
        int r = i >> 4, c = i & 15;
        float4 v = wg[r * 16 + c];
        float* dst = &ws[r * PAD + c * 4];
        dst[0] = v.x; dst[1] = v.y; dst[2] = v.z; dst[3] = v.w;
    }
    __syncthreads();

    const int warp = tid >> 5;
    const int wr = warp >> 1;        // 0..3  -> 16-row tile
    const int wc = warp & 1;         // 0..1  -> 32-col half

    wmma::fragment<wmma::accumulator, 16, 16, 8, float> acc[2];
    wmma::fill_fragment(acc[0], 0.0f);
    wmma::fill_fragment(acc[1], 0.0f);

    #pragma unroll
    for (int k = 0; k < 8; k++) {
        wmma::fragment<wmma::matrix_a, 16, 16, 8, wmma::precision::tf32, wmma::row_major> a;
        wmma::load_matrix_sync(a, &xs[(wr * 16) * PAD + k * 8], PAD);
        #pragma unroll
        for (int e = 0; e < a.num_elements; e++) a.x[e] = wmma::__float_to_tf32(a.x[e]);

        #pragma unroll
        for (int n = 0; n < 2; n++) {
            wmma::fragment<wmma::matrix_b, 16, 16, 8, wmma::precision::tf32, wmma::row_major> bfr;
            wmma::load_matrix_sync(bfr, &ws[(k * 8) * PAD + wc * 32 + n * 16], PAD);
            #pragma unroll
            for (int e = 0; e < bfr.num_elements; e++) bfr.x[e] = wmma::__float_to_tf32(bfr.x[e]);
            wmma::mma_sync(acc[n], a, bfr, acc[n]);
        }
    }

    #pragma unroll
    for (int n = 0; n < 2; n++) {
        float* out = g_xz + (row0 + wr * 16) * G4 + wc * 32 + n * 16;
        wmma::store_matrix_sync(out, acc[n], G4, wmma::mem_row_major);
    }
}

// ---------------------------------------------------------------------------
// Kernel B: LSTM recurrence + MLP head. One warp per batch row.
// Lane l owns gates l and l+32 (gate order i[0:16] f[16:32] g[32:48] o[48:64]).
// ---------------------------------------------------------------------------
__device__ __forceinline__ float sigmoidf_fast(float x) {
    return __fdividef(1.0f, 1.0f + __expf(-x));
}

__global__ __launch_bounds__(256) void lstm_rec_kernel(
    const float* __restrict__ Wh, const float* __restrict__ b,
    const float* __restrict__ W2, const float* __restrict__ b2,
    const float* __restrict__ W3, const float* __restrict__ b3,
    const float* __restrict__ Wo, const float* __restrict__ bo,
    float* __restrict__ out)
{
    const int lane = threadIdx.x & 31;
    const int warp = threadIdx.x >> 5;
    const int bb = blockIdx.x * 8 + warp;     // batch row, grid = 256 blocks

    // Per-lane Wh columns in registers
    float whA[HH], whB[HH];
    #pragma unroll
    for (int j = 0; j < HH; j++) {
        whA[j] = Wh[j * G4 + lane];
        whB[j] = Wh[j * G4 + lane + 32];
    }
    const float biasA = b[lane];
    const float biasB = b[lane + 32];

    const float* rowbase = g_xz + (long)bb * TT * G4;

    float h = 0.0f, c = 0.0f;
    float za = rowbase[lane];
    float zb = rowbase[lane + 32];

    for (int t = 0; t < TT; t++) {
        // prefetch next timestep
        float zaN = 0.0f, zbN = 0.0f;
        if (t < TT - 1) {
            const float* p = rowbase + (t + 1) * G4;
            zaN = p[lane];
            zbN = p[lane + 32];
        }

        za += biasA;
        zb += biasB;

        // z += h @ Wh  (h broadcast from lanes 0..15)
        #pragma unroll
        for (int j = 0; j < HH; j++) {
            float hj = __shfl_sync(0xffffffffu, h, j);
            za = fmaf(hj, whA[j], za);
            zb = fmaf(hj, whB[j], zb);
        }

        // activations: lane<16 -> (i, g); lane>=16 -> (f, o)
        float sa = sigmoidf_fast(za);           // i (lanes<16) or f (lanes>=16)
        float sb = sigmoidf_fast(zb);           // o on lanes>=16
        float rb = fmaxf(zb, 0.0f);             // g on lanes<16

        int j = lane & 15;
        float iv = __shfl_sync(0xffffffffu, sa, j);
        float fv = __shfl_sync(0xffffffffu, sa, j + 16);
        float gv = __shfl_sync(0xffffffffu, rb, j);
        float ov = __shfl_sync(0xffffffffu, sb, j + 16);

        c = fmaf(fv, c, iv * gv);
        h = ov * fmaxf(c, 0.0f);

        za = zaN;
        zb = zbN;
    }

    // Gather final h and run the MLP head on lane 0
    float hv[HH];
    #pragma unroll
    for (int j = 0; j < HH; j++) hv[j] = __shfl_sync(0xffffffffu, h, j);

    if (lane == 0) {
        float x2[8];
        #pragma unroll
        for (int k = 0; k < 8; k++) {
            float s = b2[k];
            #pragma unroll
            for (int j = 0; j < HH; j++) s = fmaf(hv[j], W2[j * 8 + k], s);
            x2[k] = fmaxf(s, 0.0f);
        }
        float x3[4];
        #pragma unroll
        for (int m = 0; m < 4; m++) {
            float s = b3[m];
            #pragma unroll
            for (int k = 0; k < 8; k++) s = fmaf(x2[k], W3[k * 4 + m], s);
            x3[m] = fmaxf(s, 0.0f);
        }
        float s = bo[0];
        #pragma unroll
        for (int m = 0; m < 4; m++) s = fmaf(x3[m], Wo[m], s);
        out[bb] = sigmoidf_fast(s);
    }
}

// ---------------------------------------------------------------------------
// Launch
// ---------------------------------------------------------------------------
extern "C" void kernel_launch(void* const* d_in, const int* in_sizes, int n_in,
                              void* d_out, int out_size)
{
    const float* x  = (const float*)d_in[0];   // [B, T, F]
    const float* Wx = (const float*)d_in[1];   // [F, 4H]
    const float* Wh = (const float*)d_in[2];   // [H, 4H]
    const float* b  = (const float*)d_in[3];   // [4H]
    const float* W2 = (const float*)d_in[4];   // [H, 8]
    const float* b2 = (const float*)d_in[5];   // [8]
    const float* W3 = (const float*)d_in[6];   // [8, 4]
    const float* b3 = (const float*)d_in[7];   // [4]
    const float* Wo = (const float*)d_in[8];   // [4, 1]
    const float* bo = (const float*)d_in[9];   // [1]
    float* out = (float*)d_out;                // [B, 1]

    xz_gemm_kernel<<<BT / ROWS_PER_BLK, 256>>>(x, Wx);
    lstm_rec_kernel<<<BB / 8, 256>>>(Wh, b, W2, b2, W3, b3, Wo, bo, out);
}

// round 5
// speedup vs baseline: 1.3988x; 1.3988x over previous
#include <cuda_runtime.h>
#include <cuda_fp16.h>
#include <mma.h>

using namespace nvcuda;

// Problem constants
#define BB   2048
#define TT   512
#define FF   64
#define HH   16
#define G4   64            // 4*H
#define BT   (BB * TT)     // 1,048,576 rows of x

// 256 MiB scratch: xz (+bias) in fp32, transposed layout [b][gate][t] (t fastest)
__device__ float g_xz[(long)BB * G4 * TT];

// ---------------------------------------------------------------------------
// Kernel A: xz = x @ Wx + b  (tf32 WMMA), transposed fp32 store [b][gate][t]
// Tile: 64 rows (= 64 consecutive t of one b) x 64 gates, 256 threads.
// ---------------------------------------------------------------------------
#define ROWS_PER_BLK 64
#define PAD  72   // staging pad (multiple of 8 for wmma ldm)
#define ZPAD 68   // transpose-read pad: MUST be multiple of 4 for fp32 wmma store

__global__ __launch_bounds__(256) void xz_gemm_kernel(
    const float* __restrict__ x, const float* __restrict__ Wx,
    const float* __restrict__ bias)
{
    __shared__ float xs[ROWS_PER_BLK * PAD];
    __shared__ float ws[FF * PAD];
    __shared__ alignas(16) float zs[ROWS_PER_BLK * ZPAD];

    const int tid = threadIdx.x;
    const long row0 = (long)blockIdx.x * ROWS_PER_BLK;   // = b*512 + t0
    const int b  = (int)(row0 >> 9);       // row0 / 512
    const int t0 = (int)(row0 & 511);      // row0 % 512

    // Stage x tile (64x64) as float4, coalesced
    const float4* xg = (const float4*)(x + row0 * FF);
    #pragma unroll
    for (int i = tid; i < ROWS_PER_BLK * 16; i += 256) {
        int r = i >> 4, c = i & 15;
        float4 v = xg[r * 16 + c];
        float* dst = &xs[r * PAD + c * 4];
        dst[0] = v.x; dst[1] = v.y; dst[2] = v.z; dst[3] = v.w;
    }
    // Stage Wx (64x64)
    const float4* wg = (const float4*)Wx;
    #pragma unroll
    for (int i = tid; i < FF * 16; i += 256) {
        int r = i >> 4, c = i & 15;
        float4 v = wg[r * 16 + c];
        float* dst = &ws[r * PAD + c * 4];
        dst[0] = v.x; dst[1] = v.y; dst[2] = v.z; dst[3] = v.w;
    }
    __syncthreads();

    const int warp = tid >> 5;
    const int wr = warp >> 1;        // 0..3  -> 16-row tile
    const int wc = warp & 1;         // 0..1  -> 32-col half

    wmma::fragment<wmma::accumulator, 16, 16, 8, float> acc[2];
    wmma::fill_fragment(acc[0], 0.0f);
    wmma::fill_fragment(acc[1], 0.0f);

    #pragma unroll
    for (int k = 0; k < 8; k++) {
        wmma::fragment<wmma::matrix_a, 16, 16, 8, wmma::precision::tf32, wmma::row_major> a;
        wmma::load_matrix_sync(a, &xs[(wr * 16) * PAD + k * 8], PAD);
        #pragma unroll
        for (int e = 0; e < a.num_elements; e++) a.x[e] = wmma::__float_to_tf32(a.x[e]);

        #pragma unroll
        for (int n = 0; n < 2; n++) {
            wmma::fragment<wmma::matrix_b, 16, 16, 8, wmma::precision::tf32, wmma::row_major> bfr;
            wmma::load_matrix_sync(bfr, &ws[(k * 8) * PAD + wc * 32 + n * 16], PAD);
            #pragma unroll
            for (int e = 0; e < bfr.num_elements; e++) bfr.x[e] = wmma::__float_to_tf32(bfr.x[e]);
            wmma::mma_sync(acc[n], a, bfr, acc[n]);
        }
    }

    // Store accumulators to smem tile zs[t_local][gate]  (ZPAD mult-of-4: legal ldm)
    #pragma unroll
    for (int n = 0; n < 2; n++) {
        wmma::store_matrix_sync(&zs[(wr * 16) * ZPAD + wc * 32 + n * 16],
                                acc[n], ZPAD, wmma::mem_row_major);
    }
    __syncthreads();

    // Transposed fp32 write-out: 4 lanes per gate, interleaved 4-float chunks so
    // each float4 store instruction covers 64 contiguous bytes per gate.
    {
        const int gate = tid >> 2;          // 0..63
        const int m    = tid & 3;           // chunk lane
        const float bg = bias[gate];

        float* dst = g_xz + ((long)b * G4 + gate) * TT + t0;
        #pragma unroll
        for (int q = 0; q < 4; q++) {
            const int tb = q * 16 + m * 4;  // t offset of this chunk
            float4 v;
            v.x = zs[(tb + 0) * ZPAD + gate] + bg;
            v.y = zs[(tb + 1) * ZPAD + gate] + bg;
            v.z = zs[(tb + 2) * ZPAD + gate] + bg;
            v.w = zs[(tb + 3) * ZPAD + gate] + bg;
            *(float4*)(dst + tb) = v;
        }
    }
}

// ---------------------------------------------------------------------------
// Kernel B: LSTM recurrence + MLP head. One warp per batch row, 4 warps/block.
// Lane l owns gates l and l+32 (gate order i[0:16] f[16:32] g[32:48] o[48:64]).
// xz layout [b][gate][t]: lane loads 4 timesteps per float4; 8-step groups
// with next-group prefetch (~8 steps of compute covers DRAM latency).
// ---------------------------------------------------------------------------
__device__ __forceinline__ float sigmoidf_fast(float x) {
    return __fdividef(1.0f, 1.0f + __expf(-x));
}

__global__ __launch_bounds__(128) void lstm_rec_kernel(
    const float* __restrict__ Wh,
    const float* __restrict__ W2, const float* __restrict__ b2,
    const float* __restrict__ W3, const float* __restrict__ b3,
    const float* __restrict__ Wo, const float* __restrict__ bo,
    float* __restrict__ out)
{
    const int lane = threadIdx.x & 31;
    const int warp = threadIdx.x >> 5;
    const int bb = blockIdx.x * 4 + warp;     // batch row

    // Per-lane Wh columns in registers
    float whA[HH], whB[HH];
    #pragma unroll
    for (int j = 0; j < HH; j++) {
        whA[j] = Wh[j * G4 + lane];
        whB[j] = Wh[j * G4 + lane + 32];
    }

    const float* pa = g_xz + ((long)bb * G4 + lane) * TT;   // gate `lane`
    const float* pb = pa + 32 * TT;                         // gate `lane+32`

    float h = 0.0f, c = 0.0f;

    // current group (8 timesteps) = 2 float4 per stream
    float4 a0 = *(const float4*)(pa);
    float4 a1 = *(const float4*)(pa + 4);
    float4 b0 = *(const float4*)(pb);
    float4 b1 = *(const float4*)(pb + 4);

    #pragma unroll 1
    for (int grp = 0; grp < TT / 8; grp++) {
        float4 a0n, a1n, b0n, b1n;
        if (grp < TT / 8 - 1) {
            const float* qa = pa + (grp + 1) * 8;
            const float* qb = pb + (grp + 1) * 8;
            a0n = *(const float4*)(qa);
            a1n = *(const float4*)(qa + 4);
            b0n = *(const float4*)(qb);
            b1n = *(const float4*)(qb + 4);
        }

        float az[8] = {a0.x, a0.y, a0.z, a0.w, a1.x, a1.y, a1.z, a1.w};
        float bz[8] = {b0.x, b0.y, b0.z, b0.w, b1.x, b1.y, b1.z, b1.w};

        #pragma unroll
        for (int k = 0; k < 8; k++) {
            // z = xz + h @ Wh  (h broadcast from lanes 0..15, split accumulators)
            float za0 = az[k], za1 = 0.0f;
            float zb0 = bz[k], zb1 = 0.0f;
            #pragma unroll
            for (int j = 0; j < 8; j++) {
                float hj = __shfl_sync(0xffffffffu, h, j);
                za0 = fmaf(hj, whA[j], za0);
                zb0 = fmaf(hj, whB[j], zb0);
            }
            #pragma unroll
            for (int j = 8; j < 16; j++) {
                float hj = __shfl_sync(0xffffffffu, h, j);
                za1 = fmaf(hj, whA[j], za1);
                zb1 = fmaf(hj, whB[j], zb1);
            }
            float za = za0 + za1;
            float zb = zb0 + zb1;

            // activations: lane<16 -> (i, g); lane>=16 -> (f, o)
            float sa = sigmoidf_fast(za);        // i (lanes<16) or f (lanes>=16)
            float sb = sigmoidf_fast(zb);        // o on lanes>=16
            float rb = fmaxf(zb, 0.0f);          // g on lanes<16

            int j = lane & 15;
            float iv = __shfl_sync(0xffffffffu, sa, j);
            float fv = __shfl_sync(0xffffffffu, sa, j + 16);
            float gv = __shfl_sync(0xffffffffu, rb, j);
            float ov = __shfl_sync(0xffffffffu, sb, j + 16);

            c = fmaf(fv, c, iv * gv);
            h = ov * fmaxf(c, 0.0f);
        }

        a0 = a0n; a1 = a1n; b0 = b0n; b1 = b1n;
    }

    // Gather final h and run the MLP head on lane 0
    float hv[HH];
    #pragma unroll
    for (int j = 0; j < HH; j++) hv[j] = __shfl_sync(0xffffffffu, h, j);

    if (lane == 0) {
        float x2[8];
        #pragma unroll
        for (int k = 0; k < 8; k++) {
            float s = b2[k];
            #pragma unroll
            for (int j = 0; j < HH; j++) s = fmaf(hv[j], W2[j * 8 + k], s);
            x2[k] = fmaxf(s, 0.0f);
        }
        float x3[4];
        #pragma unroll
        for (int m = 0; m < 4; m++) {
            float s = b3[m];
            #pragma unroll
            for (int k = 0; k < 8; k++) s = fmaf(x2[k], W3[k * 4 + m], s);
            x3[m] = fmaxf(s, 0.0f);
        }
        float s = bo[0];
        #pragma unroll
        for (int m = 0; m < 4; m++) s = fmaf(x3[m], Wo[m], s);
        out[bb] = sigmoidf_fast(s);
    }
}

// ---------------------------------------------------------------------------
// Launch
// ---------------------------------------------------------------------------
extern "C" void kernel_launch(void* const* d_in, const int* in_sizes, int n_in,
                              void* d_out, int out_size)
{
    const float* x  = (const float*)d_in[0];   // [B, T, F]
    const float* Wx = (const float*)d_in[1];   // [F, 4H]
    const float* Wh = (const float*)d_in[2];   // [H, 4H]
    const float* b  = (const float*)d_in[3];   // [4H]
    const float* W2 = (const float*)d_in[4];   // [H, 8]
    const float* b2 = (const float*)d_in[5];   // [8]
    const float* W3 = (const float*)d_in[6];   // [8, 4]
    const float* b3 = (const float*)d_in[7];   // [4]
    const float* Wo = (const float*)d_in[8];   // [4, 1]
    const float* bo = (const float*)d_in[9];   // [1]
    float* out = (float*)d_out;                // [B, 1]

    xz_gemm_kernel<<<BT / ROWS_PER_BLK, 256>>>(x, Wx, b);
    lstm_rec_kernel<<<BB / 4, 128>>>(Wh, W2, b2, W3, b3, Wo, bo, out);
}

// round 6
// speedup vs baseline: 1.7248x; 1.2331x over previous
#include <cuda_runtime.h>
#include <cuda_fp16.h>
#include <mma.h>

using namespace nvcuda;

// Problem constants
#define BB   2048
#define TT   512
#define FF   64
#define HH   16
#define G4   64            // 4*H
#define BT   (BB * TT)     // 1,048,576 rows of x
#define TB   (TT / 4)      // 128 t-blocks of 4 steps

// 256 MiB scratch: xz (+bias) fp32, layout [bpair][tb][row01][gate][4t]
// chunk per (bpair,tb) = 2 rows * 64 gates * 4 t = 512 floats (2 KB)
__device__ float g_xz[(long)BB * G4 * TT];

// ---------------------------------------------------------------------------
// packed f32x2 helpers (Blackwell FFMA2 — PTX-only pattern)
// ---------------------------------------------------------------------------
typedef unsigned long long u64;
__device__ __forceinline__ u64 pk2(float lo, float hi) {
    u64 r; asm("mov.b64 %0, {%1, %2};" : "=l"(r) : "f"(lo), "f"(hi)); return r;
}
__device__ __forceinline__ float upk_sum(u64 v) {
    float lo, hi; asm("mov.b64 {%0, %1}, %2;" : "=f"(lo), "=f"(hi) : "l"(v));
    return lo + hi;
}
__device__ __forceinline__ u64 ffma2(u64 a, u64 b, u64 c) {
    u64 d; asm("fma.rn.f32x2 %0, %1, %2, %3;" : "=l"(d) : "l"(a), "l"(b), "l"(c));
    return d;
}

// ---------------------------------------------------------------------------
// Kernel A: xz = x @ Wx + b (tf32 WMMA), store to [bpair][tb][row][gate][4t]
// Tile: 64 rows (= 64 consecutive t of one b) x 64 gates, 256 threads.
// ---------------------------------------------------------------------------
#define ROWS_PER_BLK 64
#define PAD  72   // staging pad (multiple of 8 for wmma ldm)
#define ZPAD 68   // transpose pad: multiple of 4 for fp32 wmma store

__global__ __launch_bounds__(256) void xz_gemm_kernel(
    const float* __restrict__ x, const float* __restrict__ Wx,
    const float* __restrict__ bias)
{
    __shared__ alignas(16) float xs[ROWS_PER_BLK * PAD];   // reused as zs
    __shared__ float ws[FF * PAD];
    float* zs = xs;   // 64*68 = 4352 <= 64*72 = 4608

    const int tid = threadIdx.x;
    const long row0 = (long)blockIdx.x * ROWS_PER_BLK;   // = b*512 + t0
    const int b  = (int)(row0 >> 9);       // row0 / 512
    const int t0 = (int)(row0 & 511);      // row0 % 512

    // Stage x tile (64x64) as float4, coalesced
    const float4* xg = (const float4*)(x + row0 * FF);
    #pragma unroll
    for (int i = tid; i < ROWS_PER_BLK * 16; i += 256) {
        int r = i >> 4, c = i & 15;
        float4 v = xg[r * 16 + c];
        float* dst = &xs[r * PAD + c * 4];
        dst[0] = v.x; dst[1] = v.y; dst[2] = v.z; dst[3] = v.w;
    }
    // Stage Wx (64x64)
    const float4* wg = (const float4*)Wx;
    #pragma unroll
    for (int i = tid; i < FF * 16; i += 256) {
        int r = i >> 4, c = i & 15;
        float4 v = wg[r * 16 + c];
        float* dst = &ws[r * PAD + c * 4];
        dst[0] = v.x; dst[1] = v.y; dst[2] = v.z; dst[3] = v.w;
    }
    __syncthreads();

    const int warp = tid >> 5;
    const int wr = warp >> 1;        // 0..3  -> 16-row tile
    const int wc = warp & 1;         // 0..1  -> 32-col half

    wmma::fragment<wmma::accumulator, 16, 16, 8, float> acc[2];
    wmma::fill_fragment(acc[0], 0.0f);
    wmma::fill_fragment(acc[1], 0.0f);

    #pragma unroll
    for (int k = 0; k < 8; k++) {
        wmma::fragment<wmma::matrix_a, 16, 16, 8, wmma::precision::tf32, wmma::row_major> a;
        wmma::load_matrix_sync(a, &xs[(wr * 16) * PAD + k * 8], PAD);
        #pragma unroll
        for (int e = 0; e < a.num_elements; e++) a.x[e] = wmma::__float_to_tf32(a.x[e]);

        #pragma unroll
        for (int n = 0; n < 2; n++) {
            wmma::fragment<wmma::matrix_b, 16, 16, 8, wmma::precision::tf32, wmma::row_major> bfr;
            wmma::load_matrix_sync(bfr, &ws[(k * 8) * PAD + wc * 32 + n * 16], PAD);
            #pragma unroll
            for (int e = 0; e < bfr.num_elements; e++) bfr.x[e] = wmma::__float_to_tf32(bfr.x[e]);
            wmma::mma_sync(acc[n], a, bfr, acc[n]);
        }
    }

    __syncthreads();   // all MMA reads of xs done before zs overwrite

    // Store accumulators to smem tile zs[t_local][gate]
    #pragma unroll
    for (int n = 0; n < 2; n++) {
        wmma::store_matrix_sync(&zs[(wr * 16) * ZPAD + wc * 32 + n * 16],
                                acc[n], ZPAD, wmma::mem_row_major);
    }
    __syncthreads();

    // Write-out to [bpair][tb][row01][gate][4t].
    // thread -> tb-local = tid>>4 (16 tb's of 4 t each), base gate = tid&15 (+16m).
    {
        const int tbl = tid >> 4;           // 0..15
        const int g0  = tid & 15;           // 0..15
        const long chunk = (((long)(b >> 1) * TB + (t0 >> 2) + tbl) * 2 + (b & 1)) * 256;

        #pragma unroll
        for (int m = 0; m < 4; m++) {
            const int g = g0 + 16 * m;
            const float bg = bias[g];
            float4 v;
            v.x = zs[(tbl * 4 + 0) * ZPAD + g] + bg;
            v.y = zs[(tbl * 4 + 1) * ZPAD + g] + bg;
            v.z = zs[(tbl * 4 + 2) * ZPAD + g] + bg;
            v.w = zs[(tbl * 4 + 3) * ZPAD + g] + bg;
            *(float4*)(g_xz + chunk + g * 4) = v;
        }
    }
}

// ---------------------------------------------------------------------------
// Kernel B: LSTM recurrence + MLP head.
// 2 batch rows per warp: lanes 0-15 = row 2w units 0-15, lanes 16-31 = row 2w+1.
// Lane u computes all 4 gates of unit u (FFMA2-packed h@Wh), local c/h update.
// 16 h-broadcast shuffles per step serve both rows; zero gather shuffles.
// ---------------------------------------------------------------------------
__device__ __forceinline__ float sigmoidf_fast(float x) {
    return __fdividef(1.0f, 1.0f + __expf(-x));
}

__global__ __launch_bounds__(256) void lstm_rec_kernel(
    const float* __restrict__ Wh,
    const float* __restrict__ W2, const float* __restrict__ b2,
    const float* __restrict__ W3, const float* __restrict__ b3,
    const float* __restrict__ Wo, const float* __restrict__ bo,
    float* __restrict__ out)
{
    const int lane = threadIdx.x & 31;
    const int warp = threadIdx.x >> 5;
    const int u    = lane & 15;             // unit
    const int hsel = lane & 16;             // 0 for row0 lanes, 16 for row1 lanes
    const int bpair = blockIdx.x * 8 + warp;

    // Packed recurrent weights: wp[g][m] = (Wh[2m][gate], Wh[2m+1][gate]),
    // gate = u + 16*g  (g: 0=i, 1=f, 2=g, 3=o)
    u64 wp[4][8];
    #pragma unroll
    for (int g = 0; g < 4; g++) {
        const int gate = u + 16 * g;
        #pragma unroll
        for (int m = 0; m < 8; m++)
            wp[g][m] = pk2(Wh[(2 * m) * G4 + gate], Wh[(2 * m + 1) * G4 + gate]);
    }

    // xz base for this lane: + half-row offset + gate-group base
    const float* base = g_xz + (long)bpair * (TB * 512) + (hsel >> 4) * 256 + u * 4;

    float h = 0.0f, c = 0.0f;

    float4 cur[4], nxt[4];
    #pragma unroll
    for (int m = 0; m < 4; m++)
        cur[m] = *(const float4*)(base + 64 * m);

    #pragma unroll 1
    for (int tb = 0; tb < TB; tb++) {
        if (tb < TB - 1) {
            const float* p = base + (tb + 1) * 512;
            #pragma unroll
            for (int m = 0; m < 4; m++)
                nxt[m] = *(const float4*)(p + 64 * m);
        }

        float xi[4] = {cur[0].x, cur[0].y, cur[0].z, cur[0].w};
        float xf[4] = {cur[1].x, cur[1].y, cur[1].z, cur[1].w};
        float xg[4] = {cur[2].x, cur[2].y, cur[2].z, cur[2].w};
        float xo[4] = {cur[3].x, cur[3].y, cur[3].z, cur[3].w};

        #pragma unroll
        for (int k = 0; k < 4; k++) {
            // broadcast h of my row (src lanes hsel..hsel+15), packed in pairs
            u64 hp[8];
            #pragma unroll
            for (int m = 0; m < 8; m++) {
                float h0 = __shfl_sync(0xffffffffu, h, hsel + 2 * m);
                float h1 = __shfl_sync(0xffffffffu, h, hsel + 2 * m + 1);
                hp[m] = pk2(h0, h1);
            }

            u64 aI = pk2(xi[k], 0.0f);
            u64 aF = pk2(xf[k], 0.0f);
            u64 aG = pk2(xg[k], 0.0f);
            u64 aO = pk2(xo[k], 0.0f);
            #pragma unroll
            for (int m = 0; m < 8; m++) {
                aI = ffma2(hp[m], wp[0][m], aI);
                aF = ffma2(hp[m], wp[1][m], aF);
                aG = ffma2(hp[m], wp[2][m], aG);
                aO = ffma2(hp[m], wp[3][m], aO);
            }

            float iv = sigmoidf_fast(upk_sum(aI));
            float fv = sigmoidf_fast(upk_sum(aF));
            float gv = fmaxf(upk_sum(aG), 0.0f);
            float ov = sigmoidf_fast(upk_sum(aO));

            c = fmaf(fv, c, iv * gv);
            h = ov * fmaxf(c, 0.0f);
        }

        #pragma unroll
        for (int m = 0; m < 4; m++) cur[m] = nxt[m];
    }

    // MLP head: gather my row's h, lanes u==0 compute per-row head
    float hv[HH];
    #pragma unroll
    for (int j = 0; j < HH; j++)
        hv[j] = __shfl_sync(0xffffffffu, h, hsel + j);

    if (u == 0) {
        float x2[8];
        #pragma unroll
        for (int k = 0; k < 8; k++) {
            float s = b2[k];
            #pragma unroll
            for (int j = 0; j < HH; j++) s = fmaf(hv[j], W2[j * 8 + k], s);
            x2[k] = fmaxf(s, 0.0f);
        }
        float x3[4];
        #pragma unroll
        for (int m = 0; m < 4; m++) {
            float s = b3[m];
            #pragma unroll
            for (int k = 0; k < 8; k++) s = fmaf(x2[k], W3[k * 4 + m], s);
            x3[m] = fmaxf(s, 0.0f);
        }
        float s = bo[0];
        #pragma unroll
        for (int m = 0; m < 4; m++) s = fmaf(x3[m], Wo[m], s);
        out[bpair * 2 + (hsel >> 4)] = sigmoidf_fast(s);
    }
}

// ---------------------------------------------------------------------------
// Launch
// ---------------------------------------------------------------------------
extern "C" void kernel_launch(void* const* d_in, const int* in_sizes, int n_in,
                              void* d_out, int out_size)
{
    const float* x  = (const float*)d_in[0];   // [B, T, F]
    const float* Wx = (const float*)d_in[1];   // [F, 4H]
    const float* Wh = (const float*)d_in[2];   // [H, 4H]
    const float* b  = (const float*)d_in[3];   // [4H]
    const float* W2 = (const float*)d_in[4];   // [H, 8]
    const float* b2 = (const float*)d_in[5];   // [8]
    const float* W3 = (const float*)d_in[6];   // [8, 4]
    const float* b3 = (const float*)d_in[7];   // [4]
    const float* Wo = (const float*)d_in[8];   // [4, 1]
    const float* bo = (const float*)d_in[9];   // [1]
    float* out = (float*)d_out;                // [B, 1]

    xz_gemm_kernel<<<BT / ROWS_PER_BLK, 256>>>(x, Wx, b);
    lstm_rec_kernel<<<BB / 16, 256>>>(Wh, W2, b2, W3, b3, Wo, bo, out);
}

// round 8
// speedup vs baseline: 1.8017x; 1.0446x over previous
#include <cuda_runtime.h>
#include <cuda_fp16.h>
#include <mma.h>

using namespace nvcuda;

// Problem constants
#define BB   2048
#define TT   512
#define FF   64
#define HH   16
#define G4   64            // 4*H
#define BT   (BB * TT)     // 1,048,576 rows of x
#define TB   (TT / 4)      // 128 t-blocks of 4 steps

// 128 MiB scratch: xz (+bias) fp16, layout [bpair][tb][row01][gate][4t]
// chunk per (bpair,tb) = 2 rows * 64 gates * 4 t = 512 halves (1 KB)
__device__ __half g_xz[(long)BB * G4 * TT];

// ---------------------------------------------------------------------------
// packed f32x2 helpers (Blackwell FFMA2 — PTX-only pattern)
// ---------------------------------------------------------------------------
typedef unsigned long long u64;
__device__ __forceinline__ u64 pk2(float lo, float hi) {
    u64 r; asm("mov.b64 %0, {%1, %2};" : "=l"(r) : "f"(lo), "f"(hi)); return r;
}
__device__ __forceinline__ float upk_sum(u64 v) {
    float lo, hi; asm("mov.b64 {%0, %1}, %2;" : "=f"(lo), "=f"(hi) : "l"(v));
    return lo + hi;
}
__device__ __forceinline__ u64 ffma2(u64 a, u64 b, u64 c) {
    u64 d; asm("fma.rn.f32x2 %0, %1, %2, %3;" : "=l"(d) : "l"(a), "l"(b), "l"(c));
    return d;
}

// ---------------------------------------------------------------------------
// Kernel A: xz = x @ Wx + b (tf32 WMMA), fp16 store to [bpair][tb][row][gate][4t]
// Each block: 4 consecutive 64-row tiles (Wx staged ONCE), 256 threads.
// ---------------------------------------------------------------------------
#define ROWS_PER_BLK 64
#define NTILE 4
#define PAD  72   // staging pad (multiple of 8 for wmma ldm)
#define ZPAD 68   // transpose pad: multiple of 4 for fp32 wmma store

__global__ __launch_bounds__(256) void xz_gemm_kernel(
    const float* __restrict__ x, const float* __restrict__ Wx,
    const float* __restrict__ bias)
{
    __shared__ alignas(16) float xs[ROWS_PER_BLK * PAD];   // reused as zs
    __shared__ float ws[FF * PAD];
    float* zs = xs;   // 64*68 = 4352 <= 64*72 = 4608

    const int tid = threadIdx.x;

    // Stage Wx (64x64) once per block
    const float4* wg = (const float4*)Wx;
    #pragma unroll
    for (int i = tid; i < FF * 16; i += 256) {
        int r = i >> 4, c = i & 15;
        float4 v = wg[r * 16 + c];
        float* dst = &ws[r * PAD + c * 4];
        dst[0] = v.x; dst[1] = v.y; dst[2] = v.z; dst[3] = v.w;
    }

    const int warp = tid >> 5;
    const int wr = warp >> 1;        // 0..3  -> 16-row tile
    const int wc = warp & 1;         // 0..1  -> 32-col half

    #pragma unroll 1
    for (int it = 0; it < NTILE; it++) {
        const long row0 = ((long)blockIdx.x * NTILE + it) * ROWS_PER_BLK;
        const int b  = (int)(row0 >> 9);
        const int t0 = (int)(row0 & 511);

        __syncthreads();   // ws ready (it=0); previous epilogue done (it>0)

        // Stage x tile (64x64)
        const float4* xg = (const float4*)(x + row0 * FF);
        #pragma unroll
        for (int i = tid; i < ROWS_PER_BLK * 16; i += 256) {
            int r = i >> 4, c = i & 15;
            float4 v = xg[r * 16 + c];
            float* dst = &xs[r * PAD + c * 4];
            dst[0] = v.x; dst[1] = v.y; dst[2] = v.z; dst[3] = v.w;
        }
        __syncthreads();

        wmma::fragment<wmma::accumulator, 16, 16, 8, float> acc[2];
        wmma::fill_fragment(acc[0], 0.0f);
        wmma::fill_fragment(acc[1], 0.0f);

        #pragma unroll
        for (int k = 0; k < 8; k++) {
            wmma::fragment<wmma::matrix_a, 16, 16, 8, wmma::precision::tf32, wmma::row_major> a;
            wmma::load_matrix_sync(a, &xs[(wr * 16) * PAD + k * 8], PAD);
            #pragma unroll
            for (int e = 0; e < a.num_elements; e++) a.x[e] = wmma::__float_to_tf32(a.x[e]);

            #pragma unroll
            for (int n = 0; n < 2; n++) {
                wmma::fragment<wmma::matrix_b, 16, 16, 8, wmma::precision::tf32, wmma::row_major> bfr;
                wmma::load_matrix_sync(bfr, &ws[(k * 8) * PAD + wc * 32 + n * 16], PAD);
                #pragma unroll
                for (int e = 0; e < bfr.num_elements; e++) bfr.x[e] = wmma::__float_to_tf32(bfr.x[e]);
                wmma::mma_sync(acc[n], a, bfr, acc[n]);
            }
        }

        __syncthreads();   // all MMA reads of xs done before zs overwrite

        #pragma unroll
        for (int n = 0; n < 2; n++) {
            wmma::store_matrix_sync(&zs[(wr * 16) * ZPAD + wc * 32 + n * 16],
                                    acc[n], ZPAD, wmma::mem_row_major);
        }
        __syncthreads();

        // fp16 write-out to [bpair][tb][row01][gate][4t].
        {
            const int tbl = tid >> 4;           // 0..15
            const int g0  = tid & 15;           // 0..15
            __half* chunk = g_xz +
                (((long)(b >> 1) * TB + (t0 >> 2) + tbl) * 2 + (b & 1)) * 256;

            #pragma unroll
            for (int m = 0; m < 4; m++) {
                const int g = g0 + 16 * m;
                const float bg = bias[g];
                __half2 h01 = __floats2half2_rn(zs[(tbl * 4 + 0) * ZPAD + g] + bg,
                                                zs[(tbl * 4 + 1) * ZPAD + g] + bg);
                __half2 h23 = __floats2half2_rn(zs[(tbl * 4 + 2) * ZPAD + g] + bg,
                                                zs[(tbl * 4 + 3) * ZPAD + g] + bg);
                uint2 v;
                v.x = *(unsigned*)&h01;
                v.y = *(unsigned*)&h23;
                *(uint2*)(chunk + g * 4) = v;
            }
        }
    }
}

// ---------------------------------------------------------------------------
// Kernel B: LSTM recurrence + MLP head.
// 2 batch rows per warp: lanes 0-15 = row0 units, lanes 16-31 = row1.
// Lane u computes all 4 gates of unit u (FFMA2-packed h@Wh), local c/h update.
// fp16 xz loads: 4x LDG.64 per 4 steps, next-group prefetch.
// ---------------------------------------------------------------------------
__device__ __forceinline__ float sigmoidf_fast(float x) {
    return __fdividef(1.0f, 1.0f + __expf(-x));
}

__global__ __launch_bounds__(128) void lstm_rec_kernel(
    const float* __restrict__ Wh,
    const float* __restrict__ W2, const float* __restrict__ b2,
    const float* __restrict__ W3, const float* __restrict__ b3,
    const float* __restrict__ Wo, const float* __restrict__ bo,
    float* __restrict__ out)
{
    const int lane = threadIdx.x & 31;
    const int warp = threadIdx.x >> 5;
    const int u    = lane & 15;             // unit
    const int hsel = lane & 16;             // 0 row0 lanes, 16 row1 lanes
    const int bpair = blockIdx.x * 4 + warp;

    // Packed recurrent weights: wp[g][m] = (Wh[2m][gate], Wh[2m+1][gate])
    u64 wp[4][8];
    #pragma unroll
    for (int g = 0; g < 4; g++) {
        const int gate = u + 16 * g;
        #pragma unroll
        for (int m = 0; m < 8; m++)
            wp[g][m] = pk2(Wh[(2 * m) * G4 + gate], Wh[(2 * m + 1) * G4 + gate]);
    }

    // xz base for this lane (halves): bpair chunk + row + unit
    const __half* base = g_xz + (long)bpair * (TB * 512) + (hsel >> 4) * 256 + u * 4;

    float h = 0.0f, c = 0.0f;

    uint2 cur[4], nxt[4];
    #pragma unroll
    for (int m = 0; m < 4; m++)
        cur[m] = *(const uint2*)(base + 64 * m);

    #pragma unroll 1
    for (int tb = 0; tb < TB; tb++) {
        if (tb < TB - 1) {
            const __half* p = base + (tb + 1) * 512;
            #pragma unroll
            for (int m = 0; m < 4; m++)
                nxt[m] = *(const uint2*)(p + 64 * m);
        }

        // unpack: group m -> gate (i,f,g,o), 4 timesteps each
        float xi[4], xf[4], xg[4], xo[4];
        {
            float2 p0, p1;
            p0 = __half22float2(*(__half2*)&cur[0].x);
            p1 = __half22float2(*(__half2*)&cur[0].y);
            xi[0] = p0.x; xi[1] = p0.y; xi[2] = p1.x; xi[3] = p1.y;
            p0 = __half22float2(*(__half2*)&cur[1].x);
            p1 = __half22float2(*(__half2*)&cur[1].y);
            xf[0] = p0.x; xf[1] = p0.y; xf[2] = p1.x; xf[3] = p1.y;
            p0 = __half22float2(*(__half2*)&cur[2].x);
            p1 = __half22float2(*(__half2*)&cur[2].y);
            xg[0] = p0.x; xg[1] = p0.y; xg[2] = p1.x; xg[3] = p1.y;
            p0 = __half22float2(*(__half2*)&cur[3].x);
            p1 = __half22float2(*(__half2*)&cur[3].y);
            xo[0] = p0.x; xo[1] = p0.y; xo[2] = p1.x; xo[3] = p1.y;
        }

        #pragma unroll
        for (int k = 0; k < 4; k++) {
            u64 hp[8];
            #pragma unroll
            for (int m = 0; m < 8; m++) {
                float h0 = __shfl_sync(0xffffffffu, h, hsel + 2 * m);
                float h1 = __shfl_sync(0xffffffffu, h, hsel + 2 * m + 1);
                hp[m] = pk2(h0, h1);
            }

            u64 aI = pk2(xi[k], 0.0f);
            u64 aF = pk2(xf[k], 0.0f);
            u64 aG = pk2(xg[k], 0.0f);
            u64 aO = pk2(xo[k], 0.0f);
            #pragma unroll
            for (int m = 0; m < 8; m++) {
                aI = ffma2(hp[m], wp[0][m], aI);
                aF = ffma2(hp[m], wp[1][m], aF);
                aG = ffma2(hp[m], wp[2][m], aG);
                aO = ffma2(hp[m], wp[3][m], aO);
            }

            float iv = sigmoidf_fast(upk_sum(aI));
            float fv = sigmoidf_fast(upk_sum(aF));
            float gv = fmaxf(upk_sum(aG), 0.0f);
            float ov = sigmoidf_fast(upk_sum(aO));

            c = fmaf(fv, c, iv * gv);
            h = ov * fmaxf(c, 0.0f);
        }

        #pragma unroll
        for (int m = 0; m < 4; m++) cur[m] = nxt[m];
    }

    // MLP head: gather my row's h, lane u==0 computes per-row head
    float hv[HH];
    #pragma unroll
    for (int j = 0; j < HH; j++)
        hv[j] = __shfl_sync(0xffffffffu, h, hsel + j);

    if (u == 0) {
        float x2[8];
        #pragma unroll
        for (int k = 0; k < 8; k++) {
            float s = b2[k];
            #pragma unroll
            for (int j = 0; j < HH; j++) s = fmaf(hv[j], W2[j * 8 + k], s);
            x2[k] = fmaxf(s, 0.0f);
        }
        float x3[4];
        #pragma unroll
        for (int m = 0; m < 4; m++) {
            float s = b3[m];
            #pragma unroll
            for (int k = 0; k < 8; k++) s = fmaf(x2[k], W3[k * 4 + m], s);
            x3[m] = fmaxf(s, 0.0f);
        }
        float s = bo[0];
        #pragma unroll
        for (int m = 0; m < 4; m++) s = fmaf(x3[m], Wo[m], s);
        out[bpair * 2 + (hsel >> 4)] = sigmoidf_fast(s);
    }
}

// ---------------------------------------------------------------------------
// Launch
// ---------------------------------------------------------------------------
extern "C" void kernel_launch(void* const* d_in, const int* in_sizes, int n_in,
                              void* d_out, int out_size)
{
    const float* x  = (const float*)d_in[0];   // [B, T, F]
    const float* Wx = (const float*)d_in[1];   // [F, 4H]
    const float* Wh = (const float*)d_in[2];   // [H, 4H]
    const float* b  = (const float*)d_in[3];   // [4H]
    const float* W2 = (const float*)d_in[4];   // [H, 8]
    const float* b2 = (const float*)d_in[5];   // [8]
    const float* W3 = (const float*)d_in[6];   // [8, 4]
    const float* b3 = (const float*)d_in[7];   // [4]
    const float* Wo = (const float*)d_in[8];   // [4, 1]
    const float* bo = (const float*)d_in[9];   // [1]
    float* out = (float*)d_out;                // [B, 1]

    xz_gemm_kernel<<<BT / (ROWS_PER_BLK * NTILE), 256>>>(x, Wx, b);
    lstm_rec_kernel<<<BB / 8, 128>>>(Wh, W2, b2, W3, b3, Wo, bo, out);
}

// round 9
// speedup vs baseline: 2.3178x; 1.2865x over previous
#include <cuda_runtime.h>
#include <cuda_fp16.h>
#include <mma.h>

using namespace nvcuda;

// Problem constants
#define BB   2048
#define TT   512
#define FF   64
#define HH   16
#define G4   64            // 4*H
#define BT   (BB * TT)     // 1,048,576 rows of x
#define TB   (TT / 4)      // 128 t-blocks of 4 steps

// 128 MiB scratch: xz (+bias) fp16, layout [bpair][tb][row01][gate][4t]
__device__ __half g_xz[(long)BB * G4 * TT];

// ---------------------------------------------------------------------------
// helpers
// ---------------------------------------------------------------------------
typedef unsigned long long u64;
__device__ __forceinline__ u64 pk2(float lo, float hi) {
    u64 r; asm("mov.b64 %0, {%1, %2};" : "=l"(r) : "f"(lo), "f"(hi)); return r;
}
__device__ __forceinline__ float upk_sum(u64 v) {
    float lo, hi; asm("mov.b64 {%0, %1}, %2;" : "=f"(lo), "=f"(hi) : "l"(v));
    return lo + hi;
}
__device__ __forceinline__ u64 ffma2(u64 a, u64 b, u64 c) {
    u64 d; asm("fma.rn.f32x2 %0, %1, %2, %3;" : "=l"(d) : "l"(a), "l"(b), "l"(c));
    return d;
}
__device__ __forceinline__ unsigned smem_u32(const void* p) {
    unsigned a;
    asm("{ .reg .u64 t; cvta.to.shared.u64 t, %1; cvt.u32.u64 %0, t; }"
        : "=r"(a) : "l"(p));
    return a;
}
__device__ __forceinline__ void cp16(unsigned dst, const void* src) {
    asm volatile("cp.async.ca.shared.global [%0], [%1], 16;" :: "r"(dst), "l"(src));
}
#define CP_COMMIT() asm volatile("cp.async.commit_group;" ::: "memory")
#define CP_WAIT0()  asm volatile("cp.async.wait_group 0;" ::: "memory")

// sigmoid(x) = 0.5*tanh(0.5x)+0.5  (1 MUFU op)
__device__ __forceinline__ float sig_t(float x) {
    float t;
    asm("tanh.approx.f32 %0, %1;" : "=f"(t) : "f"(x * 0.5f));
    return fmaf(t, 0.5f, 0.5f);
}

// ---------------------------------------------------------------------------
// Kernel A: xz = x @ Wx + b (tf32 WMMA), fp16 store to [bpair][tb][row][gate][4t]
// Per block: NTILE 64-row tiles. Wx B-fragments live in registers for the whole
// block; x tiles double-buffered via cp.async.
// ---------------------------------------------------------------------------
#define NTILE 8
#define PAD  72   // x staging pad (multiple of 8)
#define ZPAD 68   // transpose pad (multiple of 4 for fp32 wmma store)
#define SMEM_A_BYTES (3 * 64 * PAD * 4)   // xs0 + xs1 + wz  = 55296 B

__global__ __launch_bounds__(256) void xz_gemm_kernel(
    const float* __restrict__ x, const float* __restrict__ Wx,
    const float* __restrict__ bias)
{
    extern __shared__ float smem[];
    float* xs0 = smem;
    float* xs1 = smem + 64 * PAD;
    float* wz  = smem + 2 * 64 * PAD;   // Wx staging, then reused as zs

    const int tid  = threadIdx.x;
    const int warp = tid >> 5;
    const int wr   = warp >> 1;   // 0..3 -> 16-row strip
    const int wc   = warp & 1;    // 0..1 -> 32-col half

    // Stage Wx (64x64) once
    const float4* wg = (const float4*)Wx;
    #pragma unroll
    for (int i = tid; i < FF * 16; i += 256) {
        int r = i >> 4, c = i & 15;
        float4 v = wg[r * 16 + c];
        float* dst = &wz[r * PAD + c * 4];
        dst[0] = v.x; dst[1] = v.y; dst[2] = v.z; dst[3] = v.w;
    }
    __syncthreads();

    // Preload all B fragments into registers (tf32)
    wmma::fragment<wmma::matrix_b, 16, 16, 8, wmma::precision::tf32, wmma::row_major> bfr[8][2];
    #pragma unroll
    for (int k = 0; k < 8; k++) {
        #pragma unroll
        for (int n = 0; n < 2; n++) {
            wmma::load_matrix_sync(bfr[k][n], &wz[(k * 8) * PAD + wc * 32 + n * 16], PAD);
            #pragma unroll
            for (int e = 0; e < bfr[k][n].num_elements; e++)
                bfr[k][n].x[e] = wmma::__float_to_tf32(bfr[k][n].x[e]);
        }
    }
    __syncthreads();   // wz free for zs reuse

    const long tile0 = (long)blockIdx.x * NTILE;

    // Prefetch tile 0
    {
        const float* src = x + tile0 * 64 * FF;
        unsigned dbase = smem_u32(xs0);
        #pragma unroll
        for (int j = 0; j < 4; j++) {
            int i = tid + j * 256;
            int r = i >> 4, c = i & 15;
            cp16(dbase + (unsigned)(r * PAD + c * 4) * 4, src + r * 64 + c * 4);
        }
        CP_COMMIT();
    }

    #pragma unroll 1
    for (int it = 0; it < NTILE; it++) {
        CP_WAIT0();
        __syncthreads();

        // Prefetch next tile into the other buffer
        if (it + 1 < NTILE) {
            const float* src = x + (tile0 + it + 1) * 64 * FF;
            unsigned dbase = smem_u32(((it + 1) & 1) ? xs1 : xs0);
            #pragma unroll
            for (int j = 0; j < 4; j++) {
                int i = tid + j * 256;
                int r = i >> 4, c = i & 15;
                cp16(dbase + (unsigned)(r * PAD + c * 4) * 4, src + r * 64 + c * 4);
            }
            CP_COMMIT();
        }

        float* xb = (it & 1) ? xs1 : xs0;

        wmma::fragment<wmma::accumulator, 16, 16, 8, float> acc[2];
        wmma::fill_fragment(acc[0], 0.0f);
        wmma::fill_fragment(acc[1], 0.0f);

        #pragma unroll
        for (int k = 0; k < 8; k++) {
            wmma::fragment<wmma::matrix_a, 16, 16, 8, wmma::precision::tf32, wmma::row_major> a;
            wmma::load_matrix_sync(a, &xb[(wr * 16) * PAD + k * 8], PAD);
            #pragma unroll
            for (int e = 0; e < a.num_elements; e++) a.x[e] = wmma::__float_to_tf32(a.x[e]);
            wmma::mma_sync(acc[0], a, bfr[k][0], acc[0]);
            wmma::mma_sync(acc[1], a, bfr[k][1], acc[1]);
        }

        __syncthreads();   // previous epilogue readers of wz are done
        wmma::store_matrix_sync(&wz[(wr * 16) * ZPAD + wc * 32],      acc[0], ZPAD, wmma::mem_row_major);
        wmma::store_matrix_sync(&wz[(wr * 16) * ZPAD + wc * 32 + 16], acc[1], ZPAD, wmma::mem_row_major);
        __syncthreads();

        // Transposed fp16 write-out to [bpair][tb][row01][gate][4t]
        {
            const long row0 = (tile0 + it) * 64;
            const int b  = (int)(row0 >> 9);
            const int t0 = (int)(row0 & 511);
            const int tbl = tid >> 4;           // 0..15
            const int g0  = tid & 15;           // 0..15
            __half* chunk = g_xz +
                (((long)(b >> 1) * TB + (t0 >> 2) + tbl) * 2 + (b & 1)) * 256;

            #pragma unroll
            for (int m = 0; m < 4; m++) {
                const int g = g0 + 16 * m;
                const float bg = bias[g];
                __half2 h01 = __floats2half2_rn(wz[(tbl * 4 + 0) * ZPAD + g] + bg,
                                                wz[(tbl * 4 + 1) * ZPAD + g] + bg);
                __half2 h23 = __floats2half2_rn(wz[(tbl * 4 + 2) * ZPAD + g] + bg,
                                                wz[(tbl * 4 + 3) * ZPAD + g] + bg);
                uint2 v;
                v.x = *(unsigned*)&h01;
                v.y = *(unsigned*)&h23;
                *(uint2*)(chunk + g * 4) = v;
            }
        }
    }
}

// ---------------------------------------------------------------------------
// Kernel B: LSTM recurrence + MLP head.
// 2 batch rows per warp; lane u computes all 4 gates of unit u via FFMA2.
// h broadcast via double-slot smem (1 STS + 1 syncwarp + 8 LDS.64 per step).
// ---------------------------------------------------------------------------
__global__ __launch_bounds__(128) void lstm_rec_kernel(
    const float* __restrict__ Wh,
    const float* __restrict__ W2, const float* __restrict__ b2,
    const float* __restrict__ W3, const float* __restrict__ b3,
    const float* __restrict__ Wo, const float* __restrict__ bo,
    float* __restrict__ out)
{
    __shared__ alignas(8) float hsm[4][2][32];   // [warp][slot][lane]

    const int lane = threadIdx.x & 31;
    const int warp = threadIdx.x >> 5;
    const int u    = lane & 15;             // unit
    const int hsel = lane & 16;             // 0 row0 lanes, 16 row1 lanes
    const int bpair = blockIdx.x * 4 + warp;

    // Packed recurrent weights: wp[g][m] = (Wh[2m][gate], Wh[2m+1][gate])
    u64 wp[4][8];
    #pragma unroll
    for (int g = 0; g < 4; g++) {
        const int gate = u + 16 * g;
        #pragma unroll
        for (int m = 0; m < 8; m++)
            wp[g][m] = pk2(Wh[(2 * m) * G4 + gate], Wh[(2 * m + 1) * G4 + gate]);
    }

    const __half* base = g_xz + (long)bpair * (TB * 512) + (hsel >> 4) * 256 + u * 4;

    float h = 0.0f, c = 0.0f;
    int p = 0;

    uint2 cur[4], nxt[4];
    #pragma unroll
    for (int m = 0; m < 4; m++)
        cur[m] = *(const uint2*)(base + 64 * m);

    #pragma unroll 1
    for (int tb = 0; tb < TB; tb++) {
        if (tb < TB - 1) {
            const __half* q = base + (tb + 1) * 512;
            #pragma unroll
            for (int m = 0; m < 4; m++)
                nxt[m] = *(const uint2*)(q + 64 * m);
        }

        // unpack: group m -> gate (i,f,g,o), 4 timesteps each
        float xi[4], xf[4], xg[4], xo[4];
        {
            float2 p0, p1;
            p0 = __half22float2(*(__half2*)&cur[0].x);
            p1 = __half22float2(*(__half2*)&cur[0].y);
            xi[0] = p0.x; xi[1] = p0.y; xi[2] = p1.x; xi[3] = p1.y;
            p0 = __half22float2(*(__half2*)&cur[1].x);
            p1 = __half22float2(*(__half2*)&cur[1].y);
            xf[0] = p0.x; xf[1] = p0.y; xf[2] = p1.x; xf[3] = p1.y;
            p0 = __half22float2(*(__half2*)&cur[2].x);
            p1 = __half22float2(*(__half2*)&cur[2].y);
            xg[0] = p0.x; xg[1] = p0.y; xg[2] = p1.x; xg[3] = p1.y;
            p0 = __half22float2(*(__half2*)&cur[3].x);
            p1 = __half22float2(*(__half2*)&cur[3].y);
            xo[0] = p0.x; xo[1] = p0.y; xo[2] = p1.x; xo[3] = p1.y;
        }

        #pragma unroll
        for (int k = 0; k < 4; k++) {
            // publish h, then read my row's 8 packed pairs (broadcast LDS.64)
            hsm[warp][p][lane] = h;
            __syncwarp();
            const u64* hp = (const u64*)&hsm[warp][p][hsel];
            p ^= 1;

            u64 aI = pk2(xi[k], 0.0f);
            u64 aF = pk2(xf[k], 0.0f);
            u64 aG = pk2(xg[k], 0.0f);
            u64 aO = pk2(xo[k], 0.0f);
            #pragma unroll
            for (int m = 0; m < 8; m++) {
                u64 hm = hp[m];
                aI = ffma2(hm, wp[0][m], aI);
                aF = ffma2(hm, wp[1][m], aF);
                aG = ffma2(hm, wp[2][m], aG);
                aO = ffma2(hm, wp[3][m], aO);
            }

            float iv = sig_t(upk_sum(aI));
            float fv = sig_t(upk_sum(aF));
            float gv = fmaxf(upk_sum(aG), 0.0f);
            float ov = sig_t(upk_sum(aO));

            c = fmaf(fv, c, iv * gv);
            h = ov * fmaxf(c, 0.0f);
        }

        #pragma unroll
        for (int m = 0; m < 4; m++) cur[m] = nxt[m];
    }

    // MLP head: gather my row's h, lane u==0 computes per-row head
    hsm[warp][p][lane] = h;
    __syncwarp();

    if (u == 0) {
        float hv[HH];
        #pragma unroll
        for (int j = 0; j < HH; j++) hv[j] = hsm[warp][p][hsel + j];

        float x2[8];
        #pragma unroll
        for (int k = 0; k < 8; k++) {
            float s = b2[k];
            #pragma unroll
            for (int j = 0; j < HH; j++) s = fmaf(hv[j], W2[j * 8 + k], s);
            x2[k] = fmaxf(s, 0.0f);
        }
        float x3[4];
        #pragma unroll
        for (int m = 0; m < 4; m++) {
            float s = b3[m];
            #pragma unroll
            for (int k = 0; k < 8; k++) s = fmaf(x2[k], W3[k * 4 + m], s);
            x3[m] = fmaxf(s, 0.0f);
        }
        float s = bo[0];
        #pragma unroll
        for (int m = 0; m < 4; m++) s = fmaf(x3[m], Wo[m], s);
        out[bpair * 2 + (hsel >> 4)] = sig_t(s);
    }
}

// ---------------------------------------------------------------------------
// Launch
// ---------------------------------------------------------------------------
extern "C" void kernel_launch(void* const* d_in, const int* in_sizes, int n_in,
                              void* d_out, int out_size)
{
    const float* x  = (const float*)d_in[0];   // [B, T, F]
    const float* Wx = (const float*)d_in[1];   // [F, 4H]
    const float* Wh = (const float*)d_in[2];   // [H, 4H]
    const float* b  = (const float*)d_in[3];   // [4H]
    const float* W2 = (const float*)d_in[4];   // [H, 8]
    const float* b2 = (const float*)d_in[5];   // [8]
    const float* W3 = (const float*)d_in[6];   // [8, 4]
    const float* b3 = (const float*)d_in[7];   // [4]
    const float* Wo = (const float*)d_in[8];   // [4, 1]
    const float* bo = (const float*)d_in[9];   // [1]
    float* out = (float*)d_out;                // [B, 1]

    cudaFuncSetAttribute(xz_gemm_kernel,
                         cudaFuncAttributeMaxDynamicSharedMemorySize, SMEM_A_BYTES);
    xz_gemm_kernel<<<BT / (64 * NTILE), 256, SMEM_A_BYTES>>>(x, Wx, b);
    lstm_rec_kernel<<<BB / 8, 128>>>(Wh, W2, b2, W3, b3, Wo, bo, out);
}